// round 8
// baseline (speedup 1.0000x reference)
#include <cuda_runtime.h>
#include <cuda_fp16.h>
#include <cstdint>

// GraphConv: out = segment_sum(x[src], dst, N) @ W2 + b2
// Pipeline: pre (detect + x->fp16 + W2 bf16-split frag table) -> fill (bucket sort)
//           -> gather (warp/node, fp16 rows, fp32 accum; resets g_cnt)
//           -> 3xBF16 mma GEMM, 16 warps (+bias; resets g_ovf_cnt)

constexpr int NN = 50000;
constexpr int FD = 128;
constexpr int NE = 600000;
constexpr int CAP = 64;
constexpr int OVF_CAP = 8192;

__device__ int g_cnt[NN];                  // static-zero initially; reset by gather
__device__ int g_adj[(size_t)NN * CAP];
__device__ int g_ovf[OVF_CAP * 2];
__device__ int g_ovf_cnt;                  // reset by gemm
__device__ int g_idx64;
__device__ __align__(16) uint32_t g_xh[(size_t)NN * 64];   // x as half2 pairs
__device__ __align__(16) uint32_t g_Ah[(size_t)NN * 64];   // agg bf16 hi plane
__device__ __align__(16) uint32_t g_Al[(size_t)NN * 64];   // agg bf16 lo plane
__device__ __align__(16) uint4 g_Bfrag[8 * 16 * 32];       // W2 frags {bh0,bh1,bl0,bl1}

// ---------------------------------------------------------------------------
__device__ __forceinline__ uint32_t pack_bf16(float lo, float hi) {
    uint32_t r;
    asm("cvt.rn.bf16x2.f32 %0, %1, %2;" : "=r"(r) : "f"(hi), "f"(lo));
    return r;
}
__device__ __forceinline__ float bf_lo(uint32_t u) { return __uint_as_float(u << 16); }
__device__ __forceinline__ float bf_hi(uint32_t u) { return __uint_as_float(u & 0xFFFF0000u); }
__device__ __forceinline__ void split2(float f0, float f1, uint32_t& h, uint32_t& l) {
    h = pack_bf16(f0, f1);
    l = pack_bf16(f0 - bf_lo(h), f1 - bf_hi(h));
}

// ---------------------------------------------------------------------------
// pre: block 0 = dtype detect; blocks [1,17) = Bfrag; blocks [17, 17+CB) = x->fp16
// ---------------------------------------------------------------------------
constexpr int CB = (NN * FD / 4 + 255) / 256;   // 6250 float4-convert blocks

__global__ void pre_kernel(const unsigned int* __restrict__ w,
                           const float* __restrict__ W2,
                           const float* __restrict__ x) {
    if (blockIdx.x == 0) {
        __shared__ int found;
        if (threadIdx.x == 0) found = 0;
        __syncthreads();
        unsigned int v = 0;
        for (int j = threadIdx.x; j < 1024; j += 256) v |= w[2 * j + 1];
        if (v) atomicOr(&found, 1);
        __syncthreads();
        if (threadIdx.x == 0) g_idx64 = found ? 0 : 1;
    } else if (blockIdx.x < 17) {
        int i = (blockIdx.x - 1) * 256 + threadIdx.x;   // 0..4095
        int lane = i & 31, nt = (i >> 5) & 15, ks = i >> 9;
        int g = lane >> 2, t = lane & 3;
        int n = nt * 8 + g, k0 = ks * 16;
        float v00 = W2[(k0 + 2 * t) * FD + n];
        float v01 = W2[(k0 + 2 * t + 1) * FD + n];
        float v10 = W2[(k0 + 2 * t + 8) * FD + n];
        float v11 = W2[(k0 + 2 * t + 9) * FD + n];
        uint4 f;
        split2(v00, v01, f.x, f.z);
        split2(v10, v11, f.y, f.w);
        g_Bfrag[i] = f;
    } else {
        int i = (blockIdx.x - 17) * 256 + threadIdx.x;  // float4 index
        if (i < NN * 32) {
            float4 v = reinterpret_cast<const float4*>(x)[i];
            __half2 h0 = __float22half2_rn(make_float2(v.x, v.y));
            __half2 h1 = __float22half2_rn(make_float2(v.z, v.w));
            uint2 o;
            o.x = *reinterpret_cast<uint32_t*>(&h0);
            o.y = *reinterpret_cast<uint32_t*>(&h1);
            reinterpret_cast<uint2*>(g_xh)[i] = o;
        }
    }
}

// ---------------------------------------------------------------------------
__global__ void fill_kernel(const void* __restrict__ ei_raw) {
    int e0 = (blockIdx.x * blockDim.x + threadIdx.x) * 2;
    int idx64 = g_idx64;
#pragma unroll
    for (int u = 0; u < 2; u++) {
        int e = e0 + u;
        if (e >= NE) break;
        int src, dst;
        if (idx64) {
            const long long* ei = reinterpret_cast<const long long*>(ei_raw);
            src = (int)ei[e];
            dst = (int)ei[NE + e];
        } else {
            const int* ei = reinterpret_cast<const int*>(ei_raw);
            src = ei[e];
            dst = ei[NE + e];
        }
        int p = atomicAdd(&g_cnt[dst], 1);
        if (p < CAP) {
            g_adj[dst * CAP + p] = src;
        } else {
            int q = atomicAdd(&g_ovf_cnt, 1);
            if (q < OVF_CAP) { g_ovf[2 * q] = src; g_ovf[2 * q + 1] = dst; }
        }
    }
}

// ---------------------------------------------------------------------------
// Gather: warp/node over fp16 rows; fp32 accumulate; emits bf16 hi/lo planes.
// Resets g_cnt[n] = 0 for next replay.
// ---------------------------------------------------------------------------
__global__ __launch_bounds__(128) void gather_kernel() {
    int n = blockIdx.x * 4 + (threadIdx.x >> 5);
    if (n >= NN) return;
    int lane = threadIdx.x & 31;

    int deg = g_cnt[n];
    if (lane == 0) g_cnt[n] = 0;
    const int* adjp = g_adj + (size_t)n * CAP;
    int a0 = adjp[lane];
    int a1 = adjp[lane + 32];

    float4 acc = make_float4(0.f, 0.f, 0.f, 0.f);

    if (deg > CAP) {            // rare overflow tail
        int cnt = g_ovf_cnt;
        if (cnt > OVF_CAP) cnt = OVF_CAP;
        for (int q = 0; q < cnt; q++) {
            if (g_ovf[2 * q + 1] == n) {
                int s = g_ovf[2 * q];
                uint2 v = *(reinterpret_cast<const uint2*>(g_xh) + (size_t)s * 32 + lane);
                float2 f0 = __half22float2(*reinterpret_cast<__half2*>(&v.x));
                float2 f1 = __half22float2(*reinterpret_cast<__half2*>(&v.y));
                acc.x += f0.x; acc.y += f0.y; acc.z += f1.x; acc.w += f1.y;
            }
        }
        deg = CAP;
    }

    const uint2* xh = reinterpret_cast<const uint2*>(g_xh);
    int j = 0;
    for (; j + 4 <= deg; j += 4) {
        int base = (j < 32) ? a0 : a1;
        int s0 = __shfl_sync(0xffffffffu, base, (j + 0) & 31);
        int s1 = __shfl_sync(0xffffffffu, base, (j + 1) & 31);
        int s2 = __shfl_sync(0xffffffffu, base, (j + 2) & 31);
        int s3 = __shfl_sync(0xffffffffu, base, (j + 3) & 31);
        uint2 v0 = xh[(size_t)s0 * 32 + lane];
        uint2 v1 = xh[(size_t)s1 * 32 + lane];
        uint2 v2 = xh[(size_t)s2 * 32 + lane];
        uint2 v3 = xh[(size_t)s3 * 32 + lane];
        float2 a00 = __half22float2(*reinterpret_cast<__half2*>(&v0.x));
        float2 a01 = __half22float2(*reinterpret_cast<__half2*>(&v0.y));
        float2 a10 = __half22float2(*reinterpret_cast<__half2*>(&v1.x));
        float2 a11 = __half22float2(*reinterpret_cast<__half2*>(&v1.y));
        float2 a20 = __half22float2(*reinterpret_cast<__half2*>(&v2.x));
        float2 a21 = __half22float2(*reinterpret_cast<__half2*>(&v2.y));
        float2 a30 = __half22float2(*reinterpret_cast<__half2*>(&v3.x));
        float2 a31 = __half22float2(*reinterpret_cast<__half2*>(&v3.y));
        acc.x += a00.x + a10.x + a20.x + a30.x;
        acc.y += a00.y + a10.y + a20.y + a30.y;
        acc.z += a01.x + a11.x + a21.x + a31.x;
        acc.w += a01.y + a11.y + a21.y + a31.y;
    }
    for (; j < deg; j++) {
        int base = (j < 32) ? a0 : a1;
        int s = __shfl_sync(0xffffffffu, base, j & 31);
        uint2 v = xh[(size_t)s * 32 + lane];
        float2 f0 = __half22float2(*reinterpret_cast<__half2*>(&v.x));
        float2 f1 = __half22float2(*reinterpret_cast<__half2*>(&v.y));
        acc.x += f0.x; acc.y += f0.y; acc.z += f1.x; acc.w += f1.y;
    }

    uint32_t h0, l0, h1, l1;
    split2(acc.x, acc.y, h0, l0);
    split2(acc.z, acc.w, h1, l1);
    *reinterpret_cast<uint2*>(g_Ah + (size_t)n * 64 + lane * 2) = make_uint2(h0, h1);
    *reinterpret_cast<uint2*>(g_Al + (size_t)n * 64 + lane * 2) = make_uint2(l0, l1);
}

// ---------------------------------------------------------------------------
// 3xBF16 GEMM, 512 threads = 16 warps, one 128-row tile per CTA.
// warp w: rows (w&7)*16..+16, col half (w>>3)*64.
// smem: Ah [0,34816) Al [34816,69632) rows 272B; Bfrag [69632,135168); bias.
// ---------------------------------------------------------------------------
constexpr int LDAB = 272;
constexpr int SM_AL = 128 * LDAB;
constexpr int SM_BF = 2 * 128 * LDAB;
constexpr int SM_BIAS = SM_BF + 65536;
constexpr int GEMM_SMEM = SM_BIAS + 512;   // 135680

__device__ __forceinline__ void mma16(float* c, uint32_t a0, uint32_t a1, uint32_t a2,
                                      uint32_t a3, uint32_t b0, uint32_t b1) {
    asm volatile(
        "mma.sync.aligned.m16n8k16.row.col.f32.bf16.bf16.f32 "
        "{%0,%1,%2,%3}, {%4,%5,%6,%7}, {%8,%9}, {%0,%1,%2,%3};"
        : "+f"(c[0]), "+f"(c[1]), "+f"(c[2]), "+f"(c[3])
        : "r"(a0), "r"(a1), "r"(a2), "r"(a3), "r"(b0), "r"(b1));
}

__global__ __launch_bounds__(512, 1) void gemm_kernel(const float* __restrict__ b2,
                                                      float* __restrict__ out) {
    extern __shared__ char smem[];
    int tid = threadIdx.x;
    int row0 = blockIdx.x * 128;

    if (blockIdx.x == 0 && tid == 0) g_ovf_cnt = 0;   // reset for next replay

    // Stage A hi/lo planes: 2048 uint4 each
    {
        const uint4* ahg = reinterpret_cast<const uint4*>(g_Ah);
        const uint4* alg = reinterpret_cast<const uint4*>(g_Al);
#pragma unroll
        for (int it = 0; it < 4; it++) {
            int idx = tid + it * 512;            // 0..2047
            int r = idx >> 4, cg = idx & 15;
            uint4 zv = make_uint4(0, 0, 0, 0);
            uint4 hv = zv, lv = zv;
            if (row0 + r < NN) {
                hv = ahg[(size_t)(row0 + r) * 16 + cg];
                lv = alg[(size_t)(row0 + r) * 16 + cg];
            }
            *reinterpret_cast<uint4*>(smem + r * LDAB + cg * 16) = hv;
            *reinterpret_cast<uint4*>(smem + SM_AL + r * LDAB + cg * 16) = lv;
        }
    }
    // Stage B fragment table
    {
        uint4* bs = reinterpret_cast<uint4*>(smem + SM_BF);
#pragma unroll
        for (int it = 0; it < 8; it++) bs[tid + it * 512] = g_Bfrag[tid + it * 512];
    }
    if (tid < FD) reinterpret_cast<float*>(smem + SM_BIAS)[tid] = b2[tid];
    __syncthreads();

    int wid = tid >> 5;
    int lane = tid & 31;
    int g = lane >> 2;
    int t = lane & 3;
    int w8 = wid & 7;
    int h = wid >> 3;

    const char* Ah_base = smem + (w8 * 16 + g) * LDAB + 4 * t;
    const char* Al_base = Ah_base + SM_AL;

    float acc[8][4];
#pragma unroll
    for (int i = 0; i < 8; i++)
#pragma unroll
        for (int j = 0; j < 4; j++) acc[i][j] = 0.f;

#pragma unroll
    for (int ks = 0; ks < 8; ks++) {
        int ko = ks * 32;
        uint32_t ah0 = *reinterpret_cast<const uint32_t*>(Ah_base + ko);
        uint32_t ah1 = *reinterpret_cast<const uint32_t*>(Ah_base + ko + 8 * LDAB);
        uint32_t ah2 = *reinterpret_cast<const uint32_t*>(Ah_base + ko + 16);
        uint32_t ah3 = *reinterpret_cast<const uint32_t*>(Ah_base + ko + 8 * LDAB + 16);
        uint32_t al0 = *reinterpret_cast<const uint32_t*>(Al_base + ko);
        uint32_t al1 = *reinterpret_cast<const uint32_t*>(Al_base + ko + 8 * LDAB);
        uint32_t al2 = *reinterpret_cast<const uint32_t*>(Al_base + ko + 16);
        uint32_t al3 = *reinterpret_cast<const uint32_t*>(Al_base + ko + 8 * LDAB + 16);

        const uint4* Bf = reinterpret_cast<const uint4*>(smem + SM_BF)
                          + ks * 512 + h * 256 + lane;
#pragma unroll
        for (int nt = 0; nt < 8; nt++) {
            uint4 b = Bf[nt * 32];
            mma16(acc[nt], ah0, ah1, ah2, ah3, b.x, b.y);   // ah*bh
            mma16(acc[nt], al0, al1, al2, al3, b.x, b.y);   // al*bh
            mma16(acc[nt], ah0, ah1, ah2, ah3, b.z, b.w);   // ah*bl
        }
    }

    const float* bias = reinterpret_cast<const float*>(smem + SM_BIAS);
    int rA = row0 + w8 * 16 + g;
    int rB = rA + 8;
#pragma unroll
    for (int nt = 0; nt < 8; nt++) {
        int col = (h * 8 + nt) * 8 + 2 * t;
        float bx = bias[col], by = bias[col + 1];
        if (rA < NN) {
            float2 v = make_float2(acc[nt][0] + bx, acc[nt][1] + by);
            *reinterpret_cast<float2*>(out + (size_t)rA * FD + col) = v;
        }
        if (rB < NN) {
            float2 v = make_float2(acc[nt][2] + bx, acc[nt][3] + by);
            *reinterpret_cast<float2*>(out + (size_t)rB * FD + col) = v;
        }
    }
}

// ---------------------------------------------------------------------------
extern "C" void kernel_launch(void* const* d_in, const int* in_sizes, int n_in,
                              void* d_out, int out_size) {
    const float* x  = (const float*)d_in[0];
    const void*  ei = d_in[1];
    // d_in[2]=edge_weight, d_in[3]=W1, d_in[4]=b1 : dead in reference
    const float* W2 = (const float*)d_in[5];
    const float* b2 = (const float*)d_in[6];
    float* out = (float*)d_out;

    cudaFuncSetAttribute(gemm_kernel, cudaFuncAttributeMaxDynamicSharedMemorySize, GEMM_SMEM);

    pre_kernel<<<17 + CB, 256>>>((const unsigned int*)ei, W2, x);
    fill_kernel<<<(NE / 2 + 255) / 256, 256>>>(ei);
    gather_kernel<<<(NN + 3) / 4, 128>>>();
    gemm_kernel<<<(NN + 127) / 128, 512, GEMM_SMEM>>>(b2, out);
}